// round 1
// baseline (speedup 1.0000x reference)
#include <cuda_runtime.h>

#define B_  512
#define C_  100
#define E_  2048
#define F_  128

#define BM 64
#define BN 128
#define BK 16

typedef unsigned long long u64t;

__device__ float g_inv_sigma[C_];

// ---- packed fp32x2 helpers (sm_103a) ----
__device__ __forceinline__ u64t fma2(u64t a, u64t b, u64t c) {
    u64t d;
    asm("fma.rn.f32x2 %0, %1, %2, %3;" : "=l"(d) : "l"(a), "l"(b), "l"(c));
    return d;
}
__device__ __forceinline__ u64t pack2(float lo, float hi) {
    u64t d;
    asm("mov.b64 %0, {%1, %2};" : "=l"(d) : "f"(lo), "f"(hi));
    return d;
}
__device__ __forceinline__ void unpack2(u64t v, float& lo, float& hi) {
    asm("mov.b64 {%0, %1}, %2;" : "=f"(lo), "=f"(hi) : "l"(v));
}

// =====================================================================
// Kernel 1: per-class spectral norm (one power-iteration step)
//   v = normalize(W^T u) ; sigma = ||W v|| ; g_inv_sigma[c] = 1/sigma
// One block per class, 256 threads.
// =====================================================================
__global__ void sigma_kernel(const float* __restrict__ W,
                             const float* __restrict__ u)
{
    int c = blockIdx.x;
    const float* Wc = W + (size_t)c * F_ * E_;

    __shared__ float su[F_];
    __shared__ float sv[E_];
    __shared__ float red[40];

    int tid  = threadIdx.x;
    int lane = tid & 31;
    int wrp  = tid >> 5;

    if (tid < F_) su[tid] = u[(size_t)c * F_ + tid];
    __syncthreads();

    // ---- Phase A: v_e = sum_f W[f,e] * u[f] ; accumulate ||v||^2 ----
    float local = 0.f;
    for (int e = tid; e < E_; e += 256) {
        float a0 = 0.f, a1 = 0.f, a2 = 0.f, a3 = 0.f;
        #pragma unroll 8
        for (int f = 0; f < F_; f += 4) {
            a0 += Wc[(size_t)(f + 0) * E_ + e] * su[f + 0];
            a1 += Wc[(size_t)(f + 1) * E_ + e] * su[f + 1];
            a2 += Wc[(size_t)(f + 2) * E_ + e] * su[f + 2];
            a3 += Wc[(size_t)(f + 3) * E_ + e] * su[f + 3];
        }
        float v = (a0 + a1) + (a2 + a3);
        sv[e] = v;
        local += v * v;
    }
    #pragma unroll
    for (int o = 16; o; o >>= 1) local += __shfl_xor_sync(0xffffffffu, local, o);
    if (lane == 0) red[wrp] = local;
    __syncthreads();
    if (tid == 0) {
        float n2 = 0.f;
        #pragma unroll
        for (int i = 0; i < 8; i++) n2 += red[i];
        red[32] = 1.f / fmaxf(sqrtf(n2), 1e-12f);
    }
    __syncthreads();
    float inv = red[32];
    for (int e = tid; e < E_; e += 256) sv[e] *= inv;
    __syncthreads();

    // ---- Phase B: t_f = sum_e W[f,e]*v[e] ; sigma = sqrt(sum_f t_f^2) ----
    float local2 = 0.f;
    for (int f = wrp; f < F_; f += 8) {
        const float* row = Wc + (size_t)f * E_;
        float a0 = 0.f, a1 = 0.f;
        #pragma unroll 4
        for (int e = lane; e < E_; e += 64) {
            a0 += row[e]      * sv[e];
            a1 += row[e + 32] * sv[e + 32];
        }
        float t = a0 + a1;
        #pragma unroll
        for (int o = 16; o; o >>= 1) t += __shfl_xor_sync(0xffffffffu, t, o);
        local2 += t * t;   // same value on all lanes after full butterfly
    }
    __syncthreads();
    if (lane == 0) red[wrp] = local2;
    __syncthreads();
    if (tid == 0) {
        float s2 = 0.f;
        #pragma unroll
        for (int i = 0; i < 8; i++) s2 += red[i];
        g_inv_sigma[c] = 1.f / sqrtf(s2);
    }
}

// =====================================================================
// Kernel 2: fused per-class GEMM + RBF epilogue.
// Block = (class c, 64 batch rows). Computes z = x*W[c]^T * inv_sigma + b
// entirely in registers, then dist2 reduce over f via warp shuffles, exp.
// Thread layout: ty = tid>>5 (8 b-groups of 8 rows), tx = tid&31 (4 f each).
// Packed f32x2 FMA accumulators: 8 rows x 2 packed (4 f) = 16 fma2/k-step.
// =====================================================================
__global__ void __launch_bounds__(256, 2)
fused_kernel(const float* __restrict__ x, const float* __restrict__ W,
             const float* __restrict__ bias, const float* __restrict__ cent,
             float* __restrict__ out)
{
    int c  = blockIdx.x;
    int bb = blockIdx.y * BM;
    const float* Wc = W + (size_t)c * F_ * E_;

    __shared__ float Xs[BK][BM + 4];   // k-major, padded (stride 68 floats)
    __shared__ float Ws[BK][BN + 4];   // k-major, padded (stride 132 floats)

    int tid = threadIdx.x;
    int tx  = tid & 31;
    int ty  = tid >> 5;

    // global-load mapping (float4 granularity)
    int xb = tid >> 2;            // 0..63 batch row within tile
    int xk = (tid & 3) * 4;       // 0,4,8,12 within BK
    int wf = tid >> 2;            // 0..63 (second row = wf+64)
    int wk = (tid & 3) * 4;

    const float4* xg  = (const float4*)(x  + (size_t)(bb + xb) * E_ + xk);
    const float4* wg0 = (const float4*)(Wc + (size_t)wf        * E_ + wk);
    const float4* wg1 = (const float4*)(Wc + (size_t)(wf + 64) * E_ + wk);

    float inv_s = g_inv_sigma[c];

    u64t acc[8][2];
    #pragma unroll
    for (int i = 0; i < 8; i++) { acc[i][0] = 0ull; acc[i][1] = 0ull; }

    // prefetch first tile into registers
    float4 px  = xg[0];
    float4 pw0 = wg0[0];
    float4 pw1 = wg1[0];

    for (int k0 = 0; k0 < E_; k0 += BK) {
        // commit prefetched tile to smem (transposed to k-major)
        Xs[xk + 0][xb] = px.x;  Xs[xk + 1][xb] = px.y;
        Xs[xk + 2][xb] = px.z;  Xs[xk + 3][xb] = px.w;
        Ws[wk + 0][wf] = pw0.x; Ws[wk + 1][wf] = pw0.y;
        Ws[wk + 2][wf] = pw0.z; Ws[wk + 3][wf] = pw0.w;
        Ws[wk + 0][wf + 64] = pw1.x; Ws[wk + 1][wf + 64] = pw1.y;
        Ws[wk + 2][wf + 64] = pw1.z; Ws[wk + 3][wf + 64] = pw1.w;
        __syncthreads();

        // prefetch next tile while computing this one
        if (k0 + BK < E_) {
            int off = (k0 + BK) >> 2;   // float4 offset within the row
            px  = xg[off];
            pw0 = wg0[off];
            pw1 = wg1[off];
        }

        #pragma unroll
        for (int kk = 0; kk < BK; kk++) {
            float4 xa  = *(const float4*)&Xs[kk][ty * 8];       // broadcast
            float4 xb4 = *(const float4*)&Xs[kk][ty * 8 + 4];   // broadcast
            float4 wv  = *(const float4*)&Ws[kk][tx * 4];
            u64t wp0 = pack2(wv.x, wv.y);
            u64t wp1 = pack2(wv.z, wv.w);
            u64t xp;
            xp = pack2(xa.x,  xa.x);  acc[0][0] = fma2(xp, wp0, acc[0][0]); acc[0][1] = fma2(xp, wp1, acc[0][1]);
            xp = pack2(xa.y,  xa.y);  acc[1][0] = fma2(xp, wp0, acc[1][0]); acc[1][1] = fma2(xp, wp1, acc[1][1]);
            xp = pack2(xa.z,  xa.z);  acc[2][0] = fma2(xp, wp0, acc[2][0]); acc[2][1] = fma2(xp, wp1, acc[2][1]);
            xp = pack2(xa.w,  xa.w);  acc[3][0] = fma2(xp, wp0, acc[3][0]); acc[3][1] = fma2(xp, wp1, acc[3][1]);
            xp = pack2(xb4.x, xb4.x); acc[4][0] = fma2(xp, wp0, acc[4][0]); acc[4][1] = fma2(xp, wp1, acc[4][1]);
            xp = pack2(xb4.y, xb4.y); acc[5][0] = fma2(xp, wp0, acc[5][0]); acc[5][1] = fma2(xp, wp1, acc[5][1]);
            xp = pack2(xb4.z, xb4.z); acc[6][0] = fma2(xp, wp0, acc[6][0]); acc[6][1] = fma2(xp, wp1, acc[6][1]);
            xp = pack2(xb4.w, xb4.w); acc[7][0] = fma2(xp, wp0, acc[7][0]); acc[7][1] = fma2(xp, wp1, acc[7][1]);
        }
        __syncthreads();
    }

    // ---- epilogue: z = acc*inv_s + bias ; dist2 = sum_f (cent - z)^2 ----
    float4 bi = *(const float4*)&bias[(size_t)c * F_ + tx * 4];
    float4 ci = *(const float4*)&cent[(size_t)c * F_ + tx * 4];

    #pragma unroll
    for (int i = 0; i < 8; i++) {
        float a0, a1, a2, a3;
        unpack2(acc[i][0], a0, a1);
        unpack2(acc[i][1], a2, a3);
        float d0 = ci.x - fmaf(a0, inv_s, bi.x);
        float d1 = ci.y - fmaf(a1, inv_s, bi.y);
        float d2 = ci.z - fmaf(a2, inv_s, bi.z);
        float d3 = ci.w - fmaf(a3, inv_s, bi.w);
        float p = fmaf(d0, d0, fmaf(d1, d1, fmaf(d2, d2, d3 * d3)));
        #pragma unroll
        for (int o = 16; o; o >>= 1) p += __shfl_xor_sync(0xffffffffu, p, o);
        if (tx == 0)
            out[(size_t)(bb + ty * 8 + i) * C_ + c] = expf(-0.5f * p);
    }
}

extern "C" void kernel_launch(void* const* d_in, const int* in_sizes, int n_in,
                              void* d_out, int out_size)
{
    const float* x = (const float*)d_in[0];   // [512,2048]
    const float* W = (const float*)d_in[1];   // [100,128,2048]
    const float* b = (const float*)d_in[2];   // [100,128]
    const float* u = (const float*)d_in[3];   // [100,128]
    const float* c = (const float*)d_in[4];   // [100,128]
    float* out = (float*)d_out;               // [512,100]

    sigma_kernel<<<C_, 256>>>(W, u);
    dim3 grid(C_, B_ / BM);
    fused_kernel<<<grid, 256>>>(x, W, b, c, out);
}

// round 4
// speedup vs baseline: 2.3682x; 2.3682x over previous
#include <cuda_runtime.h>
#include <cuda_bf16.h>
#include <cstdint>
#include <cstddef>

#define C_ 100
#define B_ 512
#define E_ 2048
#define F_ 128

#define NITER  96            // 3 terms * (2048/64) k-tiles
#define STAGE_BYTES 32768    // A(16KB) + B(16KB) per stage
#define NST 4
#define DSMEM_SIZE (NST * STAGE_BYTES + 1024)

// ---------------- device scratch ----------------
__device__ __align__(1024) __nv_bfloat16 g_xh[B_ * E_];
__device__ __align__(1024) __nv_bfloat16 g_xl[B_ * E_];
__device__ __align__(1024) __nv_bfloat16 g_wh[(size_t)C_ * F_ * E_];
__device__ __align__(1024) __nv_bfloat16 g_wl[(size_t)C_ * F_ * E_];
__device__ float g_vraw[C_ * E_];
__device__ float g_nrm2p[C_ * 4];
__device__ float g_invvn[C_];
__device__ float g_s2p[C_ * 64];
__device__ float g_inv_sigma[C_];

// ---------------- helpers ----------------
__device__ __forceinline__ uint32_t smem_u32(const void* p) {
    uint32_t a;
    asm("{ .reg .u64 t; cvta.to.shared.u64 t, %1; cvt.u32.u64 %0, t; }" : "=r"(a) : "l"(p));
    return a;
}
__device__ __forceinline__ void cp16(uint32_t dst, const void* src) {
    asm volatile("cp.async.cg.shared.global [%0], [%1], 16;" :: "r"(dst), "l"(src) : "memory");
}

// =====================================================================
// preprocessing kernels
// =====================================================================
__global__ void split_x_kernel(const float* __restrict__ x) {
    int i = (blockIdx.x * 256 + threadIdx.x) * 2;
    float2 v = *(const float2*)&x[i];
    __nv_bfloat16 h0 = __float2bfloat16(v.x);
    __nv_bfloat16 h1 = __float2bfloat16(v.y);
    __nv_bfloat16 l0 = __float2bfloat16(v.x - __bfloat162float(h0));
    __nv_bfloat16 l1 = __float2bfloat16(v.y - __bfloat162float(h1));
    *(__nv_bfloat162*)&g_xh[i] = __halves2bfloat162(h0, h1);
    *(__nv_bfloat162*)&g_xl[i] = __halves2bfloat162(l0, l1);
}

__global__ void wsplit_v_kernel(const float* __restrict__ W, const float* __restrict__ u) {
    int c = blockIdx.x, et = blockIdx.y;
    __shared__ float su[F_];
    __shared__ float red[8];
    int tid = threadIdx.x, lane = tid & 31, wrp = tid >> 5;

    if (tid < F_) su[tid] = u[c * F_ + tid];
    __syncthreads();

    int e0 = et * 512 + tid * 2;
    const float* base = W + (size_t)c * F_ * E_ + e0;
    float v0 = 0.f, v1 = 0.f;
    #pragma unroll 4
    for (int f = 0; f < F_; f++) {
        float2 w = *(const float2*)(base + (size_t)f * E_);
        float uf = su[f];
        v0 = fmaf(w.x, uf, v0);
        v1 = fmaf(w.y, uf, v1);
        __nv_bfloat16 h0 = __float2bfloat16(w.x);
        __nv_bfloat16 h1 = __float2bfloat16(w.y);
        __nv_bfloat16 l0 = __float2bfloat16(w.x - __bfloat162float(h0));
        __nv_bfloat16 l1 = __float2bfloat16(w.y - __bfloat162float(h1));
        size_t oi = (size_t)(c * F_ + f) * E_ + e0;
        *(__nv_bfloat162*)&g_wh[oi] = __halves2bfloat162(h0, h1);
        *(__nv_bfloat162*)&g_wl[oi] = __halves2bfloat162(l0, l1);
    }
    *(float2*)&g_vraw[c * E_ + e0] = make_float2(v0, v1);

    float loc = v0 * v0 + v1 * v1;
    #pragma unroll
    for (int o = 16; o; o >>= 1) loc += __shfl_xor_sync(0xffffffffu, loc, o);
    if (lane == 0) red[wrp] = loc;
    __syncthreads();
    if (tid == 0) {
        float s = 0.f;
        #pragma unroll
        for (int i = 0; i < 8; i++) s += red[i];
        g_nrm2p[c * 4 + et] = s;
    }
}

__global__ void vnorm_kernel() {
    int c = threadIdx.x;
    if (c < C_) {
        float s = g_nrm2p[c * 4] + g_nrm2p[c * 4 + 1] + g_nrm2p[c * 4 + 2] + g_nrm2p[c * 4 + 3];
        g_invvn[c] = 1.f / fmaxf(sqrtf(s), 1e-12f);
    }
}

__global__ void wv_kernel(const float* __restrict__ W) {
    int c = blockIdx.x, ft = blockIdx.y;
    __shared__ float sv[E_];
    int tid = threadIdx.x, lane = tid & 31, wrp = tid >> 5;
    float inv = g_invvn[c];
    for (int i = tid; i < E_; i += 256) sv[i] = g_vraw[c * E_ + i] * inv;
    __syncthreads();

    float s2 = 0.f;
    #pragma unroll
    for (int r = 0; r < 2; r++) {
        int f = ft * 16 + wrp * 2 + r;
        const float* row = W + ((size_t)c * F_ + f) * E_;
        float a = 0.f, b = 0.f;
        #pragma unroll 4
        for (int e = lane; e < E_; e += 64) {
            a = fmaf(row[e],      sv[e],      a);
            b = fmaf(row[e + 32], sv[e + 32], b);
        }
        float t = a + b;
        #pragma unroll
        for (int o = 16; o; o >>= 1) t += __shfl_xor_sync(0xffffffffu, t, o);
        s2 += t * t;
    }
    if (lane == 0) g_s2p[c * 64 + ft * 8 + wrp] = s2;
}

__global__ void sigma_finish_kernel() {
    int c = threadIdx.x;
    if (c < C_) {
        float s = 0.f;
        #pragma unroll
        for (int i = 0; i < 64; i++) s += g_s2p[c * 64 + i];
        g_inv_sigma[c] = 1.f / sqrtf(s);
    }
}

// =====================================================================
// Main kernel (mma.sync bf16, 3-term split): per CTA (bt, c):
//   Z[128,128] = xh*wh^T + xh*wl^T + xl*wh^T (fp32 accum)
//   out = exp(-0.5 * sum_f (cent - (Z*inv_sigma + bias))^2)
// grid (4, C_): CTAs sharing class c are adjacent -> W tiles hit L2.
// =====================================================================
__global__ void __launch_bounds__(256, 1)
mm_kernel(const float* __restrict__ bias, const float* __restrict__ cent,
          float* __restrict__ out)
{
    extern __shared__ __align__(1024) char dsm[];
    __shared__ float s_bias[F_], s_cent[F_];
    __shared__ float part[128][4];

    int bt = blockIdx.x, c = blockIdx.y;
    int tid = threadIdx.x, wid = tid >> 5, lane = tid & 31;

    if (tid < F_) {
        s_bias[tid] = bias[c * F_ + tid];
        s_cent[tid] = cent[c * F_ + tid];
    }

    uint32_t dbase = (smem_u32(dsm) + 1023u) & ~1023u;
    int warp_m = wid >> 2, warp_n = wid & 3;

    float acc[4][4][4];
    #pragma unroll
    for (int mt = 0; mt < 4; mt++)
        #pragma unroll
        for (int nt = 0; nt < 4; nt++)
            #pragma unroll
            for (int q = 0; q < 4; q++) acc[mt][nt][q] = 0.f;

    const __nv_bfloat16* xsrc[3] = { g_xh, g_xh, g_xl };
    const __nv_bfloat16* wsrc[3] = { g_wh, g_wl, g_wh };

    int r0 = tid >> 3, kc = tid & 7;
    uint32_t dcol = (uint32_t)((kc ^ (r0 & 7)) * 16);

#define STAGE_ADDR(s) (dbase + (uint32_t)(s) * (uint32_t)STAGE_BYTES)
#define LOAD_STAGE(slot, itv) do { \
    int _term = (itv) >> 5; int _k0 = ((itv) & 31) << 6; \
    const __nv_bfloat16* _as = xsrc[_term] + (size_t)(bt * 128 + r0) * E_ + _k0 + kc * 8; \
    const __nv_bfloat16* _bs = wsrc[_term] + (size_t)(c * 128 + r0) * E_ + _k0 + kc * 8; \
    uint32_t _da = STAGE_ADDR(slot) + (uint32_t)r0 * 128u + dcol; \
    _Pragma("unroll") \
    for (int _j = 0; _j < 4; _j++) { \
        cp16(_da + _j * 4096u,          _as + (size_t)_j * 32 * E_); \
        cp16(_da + 16384u + _j * 4096u, _bs + (size_t)_j * 32 * E_); \
    } \
    asm volatile("cp.async.commit_group;" ::: "memory"); \
} while (0)

    LOAD_STAGE(0, 0);
    LOAD_STAGE(1, 1);
    LOAD_STAGE(2, 2);

    for (int it = 0; it < NITER; it++) {
        int s = it & 3;
        if (it + NST - 1 < NITER) LOAD_STAGE((it + NST - 1) & 3, it + NST - 1);
        if (it < NITER - (NST - 1)) asm volatile("cp.async.wait_group 3;" ::: "memory");
        else                        asm volatile("cp.async.wait_group 0;" ::: "memory");
        __syncthreads();

        uint32_t Ab = STAGE_ADDR(s), Bb = Ab + 16384u;

        #pragma unroll
        for (int kk = 0; kk < 4; kk++) {
            uint32_t bfr[4][2];
            #pragma unroll
            for (int g = 0; g < 2; g++) {
                int mat = lane >> 3, rr = lane & 7;
                int rown = warp_n * 32 + g * 16 + ((mat >> 1) << 3) + rr;
                int kcb = kk * 2 + (mat & 1);
                uint32_t addr = Bb + (uint32_t)rown * 128u + (uint32_t)((kcb ^ (rown & 7)) << 4);
                uint32_t q0, q1, q2, q3;
                asm volatile("ldmatrix.sync.aligned.m8n8.x4.shared.b16 {%0,%1,%2,%3}, [%4];"
                             : "=r"(q0), "=r"(q1), "=r"(q2), "=r"(q3) : "r"(addr));
                bfr[g * 2 + 0][0] = q0; bfr[g * 2 + 0][1] = q1;
                bfr[g * 2 + 1][0] = q2; bfr[g * 2 + 1][1] = q3;
            }
            #pragma unroll
            for (int mt = 0; mt < 4; mt++) {
                int rowm = warp_m * 64 + mt * 16 + ((lane >> 3) & 1) * 8 + (lane & 7);
                int kca = kk * 2 + (lane >> 4);
                uint32_t addr = Ab + (uint32_t)rowm * 128u + (uint32_t)((kca ^ (rowm & 7)) << 4);
                uint32_t a0, a1, a2, a3;
                asm volatile("ldmatrix.sync.aligned.m8n8.x4.shared.b16 {%0,%1,%2,%3}, [%4];"
                             : "=r"(a0), "=r"(a1), "=r"(a2), "=r"(a3) : "r"(addr));
                #pragma unroll
                for (int nt = 0; nt < 4; nt++) {
                    asm volatile(
                        "mma.sync.aligned.m16n8k16.row.col.f32.bf16.bf16.f32 "
                        "{%0,%1,%2,%3}, {%4,%5,%6,%7}, {%8,%9}, {%0,%1,%2,%3};"
                        : "+f"(acc[mt][nt][0]), "+f"(acc[mt][nt][1]),
                          "+f"(acc[mt][nt][2]), "+f"(acc[mt][nt][3])
                        : "r"(a0), "r"(a1), "r"(a2), "r"(a3),
                          "r"(bfr[nt][0]), "r"(bfr[nt][1]));
                }
            }
        }
        __syncthreads();
    }
#undef LOAD_STAGE
#undef STAGE_ADDR

    // epilogue: dist2 partial per (m row, warp_n), then combine
    float inv_s = g_inv_sigma[c];
    int rgrp = lane >> 2, qc = lane & 3;
    #pragma unroll
    for (int mt = 0; mt < 4; mt++) {
        #pragma unroll
        for (int half = 0; half < 2; half++) {
            float sum = 0.f;
            #pragma unroll
            for (int nt = 0; nt < 4; nt++) {
                int f0 = warp_n * 32 + nt * 8 + qc * 2;
                float v0 = acc[mt][nt][half * 2 + 0];
                float v1 = acc[mt][nt][half * 2 + 1];
                float d0 = s_cent[f0]     - fmaf(v0, inv_s, s_bias[f0]);
                float d1 = s_cent[f0 + 1] - fmaf(v1, inv_s, s_bias[f0 + 1]);
                sum = fmaf(d0, d0, sum);
                sum = fmaf(d1, d1, sum);
            }
            sum += __shfl_xor_sync(0xffffffffu, sum, 1);
            sum += __shfl_xor_sync(0xffffffffu, sum, 2);
            if (qc == 0)
                part[warp_m * 64 + mt * 16 + half * 8 + rgrp][warp_n] = sum;
        }
    }
    __syncthreads();
    if (tid < 128) {
        float dist2 = part[tid][0] + part[tid][1] + part[tid][2] + part[tid][3];
        out[(size_t)(bt * 128 + tid) * C_ + c] = expf(-0.5f * dist2);
    }
}

// =====================================================================
// Host
// =====================================================================
extern "C" void kernel_launch(void* const* d_in, const int* in_sizes, int n_in,
                              void* d_out, int out_size)
{
    const float* x = (const float*)d_in[0];   // [512,2048]
    const float* W = (const float*)d_in[1];   // [100,128,2048]
    const float* b = (const float*)d_in[2];   // [100,128]
    const float* u = (const float*)d_in[3];   // [100,128]
    const float* c = (const float*)d_in[4];   // [100,128]
    float* out = (float*)d_out;               // [512,100]

    cudaFuncSetAttribute(mm_kernel, cudaFuncAttributeMaxDynamicSharedMemorySize, DSMEM_SIZE);

    split_x_kernel<<<(B_ * E_) / 512, 256>>>(x);
    wsplit_v_kernel<<<dim3(C_, 4), 256>>>(W, u);
    vnorm_kernel<<<1, 128>>>();
    wv_kernel<<<dim3(C_, 8), 256>>>(W);
    sigma_finish_kernel<<<1, 128>>>();
    mm_kernel<<<dim3(4, C_), 256, DSMEM_SIZE>>>(b, c, out);
}

// round 5
// speedup vs baseline: 2.4844x; 1.0490x over previous
#include <cuda_runtime.h>
#include <cuda_bf16.h>
#include <cstdint>
#include <cstddef>

#define C_ 100
#define B_ 512
#define E_ 2048
#define F_ 128

#define NKT 32                 // k-tiles of 64
#define STAGE_BYTES 65536      // XH,XL,WH,WL tiles (16KB each)
#define DSMEM_SIZE (3 * STAGE_BYTES)

// ---------------- device scratch ----------------
__device__ __align__(1024) __nv_bfloat16 g_xh[B_ * E_];
__device__ __align__(1024) __nv_bfloat16 g_xl[B_ * E_];
__device__ __align__(1024) __nv_bfloat16 g_wh[(size_t)C_ * F_ * E_];
__device__ __align__(1024) __nv_bfloat16 g_wl[(size_t)C_ * F_ * E_];
__device__ float g_vraw[C_ * E_];
__device__ float g_nrm2p[C_ * 2];
__device__ float g_s2p[C_ * 64];

// ---------------- helpers ----------------
__device__ __forceinline__ uint32_t smem_u32(const void* p) {
    uint32_t a;
    asm("{ .reg .u64 t; cvta.to.shared.u64 t, %1; cvt.u32.u64 %0, t; }" : "=r"(a) : "l"(p));
    return a;
}
__device__ __forceinline__ void cp16(uint32_t dst, const void* src) {
    asm volatile("cp.async.cg.shared.global [%0], [%1], 16;" :: "r"(dst), "l"(src) : "memory");
}

// =====================================================================
// split x into bf16 hi/lo
// =====================================================================
__global__ void split_x_kernel(const float* __restrict__ x) {
    int i = (blockIdx.x * 256 + threadIdx.x) * 2;
    float2 v = *(const float2*)&x[i];
    __nv_bfloat16 h0 = __float2bfloat16(v.x);
    __nv_bfloat16 h1 = __float2bfloat16(v.y);
    __nv_bfloat16 l0 = __float2bfloat16(v.x - __bfloat162float(h0));
    __nv_bfloat16 l1 = __float2bfloat16(v.y - __bfloat162float(h1));
    *(__nv_bfloat162*)&g_xh[i] = __halves2bfloat162(h0, h1);
    *(__nv_bfloat162*)&g_xl[i] = __halves2bfloat162(l0, l1);
}

// =====================================================================
// fused: W -> bf16 hi/lo split AND v_raw = W^T u with partial ||v||^2
// grid (C, 2), 256 threads; block owns e-range of 1024 (4 e per thread)
// =====================================================================
__global__ void wsplit_v_kernel(const float* __restrict__ W, const float* __restrict__ u) {
    int c = blockIdx.x, et = blockIdx.y;
    __shared__ float su[F_];
    __shared__ float red[8];
    int tid = threadIdx.x, lane = tid & 31, wrp = tid >> 5;

    if (tid < F_) su[tid] = u[c * F_ + tid];
    __syncthreads();

    int e0 = et * 1024 + tid * 4;
    const float* base = W + (size_t)c * F_ * E_ + e0;
    float v0 = 0.f, v1 = 0.f, v2 = 0.f, v3 = 0.f;
    #pragma unroll 2
    for (int f = 0; f < F_; f++) {
        float4 w = *(const float4*)(base + (size_t)f * E_);
        float uf = su[f];
        v0 = fmaf(w.x, uf, v0);
        v1 = fmaf(w.y, uf, v1);
        v2 = fmaf(w.z, uf, v2);
        v3 = fmaf(w.w, uf, v3);
        __nv_bfloat16 h0 = __float2bfloat16(w.x);
        __nv_bfloat16 h1 = __float2bfloat16(w.y);
        __nv_bfloat16 h2 = __float2bfloat16(w.z);
        __nv_bfloat16 h3 = __float2bfloat16(w.w);
        __nv_bfloat16 l0 = __float2bfloat16(w.x - __bfloat162float(h0));
        __nv_bfloat16 l1 = __float2bfloat16(w.y - __bfloat162float(h1));
        __nv_bfloat16 l2 = __float2bfloat16(w.z - __bfloat162float(h2));
        __nv_bfloat16 l3 = __float2bfloat16(w.w - __bfloat162float(h3));
        size_t oi = (size_t)(c * F_ + f) * E_ + e0;
        *(__nv_bfloat162*)&g_wh[oi]     = __halves2bfloat162(h0, h1);
        *(__nv_bfloat162*)&g_wh[oi + 2] = __halves2bfloat162(h2, h3);
        *(__nv_bfloat162*)&g_wl[oi]     = __halves2bfloat162(l0, l1);
        *(__nv_bfloat162*)&g_wl[oi + 2] = __halves2bfloat162(l2, l3);
    }
    float4 vv = make_float4(v0, v1, v2, v3);
    *(float4*)&g_vraw[c * E_ + e0] = vv;

    float loc = v0 * v0 + v1 * v1 + v2 * v2 + v3 * v3;
    #pragma unroll
    for (int o = 16; o; o >>= 1) loc += __shfl_xor_sync(0xffffffffu, loc, o);
    if (lane == 0) red[wrp] = loc;
    __syncthreads();
    if (tid == 0) {
        float s = 0.f;
        #pragma unroll
        for (int i = 0; i < 8; i++) s += red[i];
        g_nrm2p[c * 2 + et] = s;
    }
}

// =====================================================================
// t = W v_hat; partial sum of t^2. grid (C, 8), 256 threads.
// warp w handles rows ft*16 + w*2 + {0,1}; float4 loads, vnorm folded in.
// =====================================================================
__global__ void wv_kernel(const float* __restrict__ W) {
    int c = blockIdx.x, ft = blockIdx.y;
    __shared__ float sv[E_];
    __shared__ float s_inv;
    int tid = threadIdx.x, lane = tid & 31, wrp = tid >> 5;

    if (tid == 0)
        s_inv = 1.f / fmaxf(sqrtf(g_nrm2p[c * 2] + g_nrm2p[c * 2 + 1]), 1e-12f);
    __syncthreads();
    float inv = s_inv;
    for (int i = tid * 4; i < E_; i += 1024) {
        float4 v = *(const float4*)&g_vraw[c * E_ + i];
        v.x *= inv; v.y *= inv; v.z *= inv; v.w *= inv;
        *(float4*)&sv[i] = v;
    }
    __syncthreads();

    int f0 = ft * 16 + wrp * 2;
    const float* p0 = W + ((size_t)c * F_ + f0) * E_;
    const float* p1 = p0 + E_;
    float t0 = 0.f, t1 = 0.f;
    #pragma unroll 4
    for (int e = lane * 4; e < E_; e += 128) {
        float4 a = *(const float4*)(p0 + e);
        float4 b = *(const float4*)(p1 + e);
        float4 v = *(const float4*)&sv[e];
        t0 = fmaf(a.x, v.x, t0); t0 = fmaf(a.y, v.y, t0);
        t0 = fmaf(a.z, v.z, t0); t0 = fmaf(a.w, v.w, t0);
        t1 = fmaf(b.x, v.x, t1); t1 = fmaf(b.y, v.y, t1);
        t1 = fmaf(b.z, v.z, t1); t1 = fmaf(b.w, v.w, t1);
    }
    #pragma unroll
    for (int o = 16; o; o >>= 1) {
        t0 += __shfl_xor_sync(0xffffffffu, t0, o);
        t1 += __shfl_xor_sync(0xffffffffu, t1, o);
    }
    if (lane == 0) g_s2p[c * 64 + ft * 8 + wrp] = t0 * t0 + t1 * t1;
}

// =====================================================================
// Main kernel (fused-term mma.sync bf16): per CTA (bt, c):
//   Z[128,128] = xh*wh^T + xh*wl^T + xl*wh^T (fp32 accum)
//   out = exp(-0.5 * sum_f (cent - (Z*inv_sigma + bias))^2)
// One 64KB stage holds {XH,XL,WH,WL} for one 64-wide k-tile; 3 stages.
// =====================================================================
__global__ void __launch_bounds__(256, 1)
mm_kernel(const float* __restrict__ bias, const float* __restrict__ cent,
          float* __restrict__ out)
{
    extern __shared__ __align__(1024) char dsm[];
    __shared__ float s_bias[F_], s_cent[F_];
    __shared__ float part[128][4];
    __shared__ float s_invs;

    int bt = blockIdx.x, c = blockIdx.y;
    int tid = threadIdx.x, wid = tid >> 5, lane = tid & 31;

    if (tid < F_) {
        s_bias[tid] = bias[c * F_ + tid];
        s_cent[tid] = cent[c * F_ + tid];
    }
    // fold sigma_finish: warp 0 reduces the 64 partials
    if (wid == 0) {
        float s = g_s2p[c * 64 + lane] + g_s2p[c * 64 + 32 + lane];
        #pragma unroll
        for (int o = 16; o; o >>= 1) s += __shfl_xor_sync(0xffffffffu, s, o);
        if (lane == 0) s_invs = 1.f / sqrtf(s);
    }

    uint32_t dbase = smem_u32(dsm);
    int warp_m = wid >> 2, warp_n = wid & 3;

    float acc[4][4][4];
    #pragma unroll
    for (int mt = 0; mt < 4; mt++)
        #pragma unroll
        for (int nt = 0; nt < 4; nt++)
            #pragma unroll
            for (int q = 0; q < 4; q++) acc[mt][nt][q] = 0.f;

    int r0 = tid >> 3, kc = tid & 7;
    uint32_t dcol = (uint32_t)((kc ^ (r0 & 7)) * 16);
    uint32_t drow = (uint32_t)r0 * 128u + dcol;

    const __nv_bfloat16* xh_s = g_xh + (size_t)(bt * 128 + r0) * E_ + kc * 8;
    const __nv_bfloat16* xl_s = g_xl + (size_t)(bt * 128 + r0) * E_ + kc * 8;
    const __nv_bfloat16* wh_s = g_wh + (size_t)(c * 128 + r0) * E_ + kc * 8;
    const __nv_bfloat16* wl_s = g_wl + (size_t)(c * 128 + r0) * E_ + kc * 8;

#define STAGE_ADDR(s) (dbase + (uint32_t)(s) * (uint32_t)STAGE_BYTES)
#define LOAD_STAGE(slot, kt) do { \
    int _k0 = (kt) << 6; \
    uint32_t _da = STAGE_ADDR(slot) + drow; \
    _Pragma("unroll") \
    for (int _j = 0; _j < 4; _j++) { \
        cp16(_da          + _j * 4096u, xh_s + _k0 + (size_t)_j * 32 * E_); \
        cp16(_da + 16384u + _j * 4096u, xl_s + _k0 + (size_t)_j * 32 * E_); \
        cp16(_da + 32768u + _j * 4096u, wh_s + _k0 + (size_t)_j * 32 * E_); \
        cp16(_da + 49152u + _j * 4096u, wl_s + _k0 + (size_t)_j * 32 * E_); \
    } \
    asm volatile("cp.async.commit_group;" ::: "memory"); \
} while (0)

    LOAD_STAGE(0, 0);
    LOAD_STAGE(1, 1);

    for (int it = 0; it < NKT; it++) {
        int s = it % 3;
        if (it == NKT - 1) asm volatile("cp.async.wait_group 0;" ::: "memory");
        else               asm volatile("cp.async.wait_group 1;" ::: "memory");
        __syncthreads();
        if (it + 2 < NKT) LOAD_STAGE((it + 2) % 3, it + 2);

        uint32_t XH = STAGE_ADDR(s);
        uint32_t XL = XH + 16384u;
        uint32_t WH = XH + 32768u;
        uint32_t WL = XH + 49152u;

        #pragma unroll
        for (int kk = 0; kk < 4; kk++) {
            // B fragments: wh and wl, 4 n-tiles each
            uint32_t bh[4][2], bl[4][2];
            int mat = lane >> 3, rr = lane & 7;
            int kcb = kk * 2 + (mat & 1);
            #pragma unroll
            for (int g = 0; g < 2; g++) {
                int rown = warp_n * 32 + g * 16 + ((mat >> 1) << 3) + rr;
                uint32_t off = (uint32_t)rown * 128u + (uint32_t)((kcb ^ (rown & 7)) << 4);
                uint32_t q0, q1, q2, q3;
                asm volatile("ldmatrix.sync.aligned.m8n8.x4.shared.b16 {%0,%1,%2,%3}, [%4];"
                             : "=r"(q0), "=r"(q1), "=r"(q2), "=r"(q3) : "r"(WH + off));
                bh[g * 2 + 0][0] = q0; bh[g * 2 + 0][1] = q1;
                bh[g * 2 + 1][0] = q2; bh[g * 2 + 1][1] = q3;
                asm volatile("ldmatrix.sync.aligned.m8n8.x4.shared.b16 {%0,%1,%2,%3}, [%4];"
                             : "=r"(q0), "=r"(q1), "=r"(q2), "=r"(q3) : "r"(WL + off));
                bl[g * 2 + 0][0] = q0; bl[g * 2 + 0][1] = q1;
                bl[g * 2 + 1][0] = q2; bl[g * 2 + 1][1] = q3;
            }
            // A fragments per m-tile, immediately consumed
            int kca = kk * 2 + (lane >> 4);
            #pragma unroll
            for (int mt = 0; mt < 4; mt++) {
                int rowm = warp_m * 64 + mt * 16 + ((lane >> 3) & 1) * 8 + (lane & 7);
                uint32_t off = (uint32_t)rowm * 128u + (uint32_t)((kca ^ (rowm & 7)) << 4);
                uint32_t a0, a1, a2, a3;
                asm volatile("ldmatrix.sync.aligned.m8n8.x4.shared.b16 {%0,%1,%2,%3}, [%4];"
                             : "=r"(a0), "=r"(a1), "=r"(a2), "=r"(a3) : "r"(XH + off));
                #pragma unroll
                for (int nt = 0; nt < 4; nt++) {
                    asm volatile(
                        "mma.sync.aligned.m16n8k16.row.col.f32.bf16.bf16.f32 "
                        "{%0,%1,%2,%3}, {%4,%5,%6,%7}, {%8,%9}, {%0,%1,%2,%3};"
                        : "+f"(acc[mt][nt][0]), "+f"(acc[mt][nt][1]),
                          "+f"(acc[mt][nt][2]), "+f"(acc[mt][nt][3])
                        : "r"(a0), "r"(a1), "r"(a2), "r"(a3),
                          "r"(bh[nt][0]), "r"(bh[nt][1]));
                    asm volatile(
                        "mma.sync.aligned.m16n8k16.row.col.f32.bf16.bf16.f32 "
                        "{%0,%1,%2,%3}, {%4,%5,%6,%7}, {%8,%9}, {%0,%1,%2,%3};"
                        : "+f"(acc[mt][nt][0]), "+f"(acc[mt][nt][1]),
                          "+f"(acc[mt][nt][2]), "+f"(acc[mt][nt][3])
                        : "r"(a0), "r"(a1), "r"(a2), "r"(a3),
                          "r"(bl[nt][0]), "r"(bl[nt][1]));
                }
                asm volatile("ldmatrix.sync.aligned.m8n8.x4.shared.b16 {%0,%1,%2,%3}, [%4];"
                             : "=r"(a0), "=r"(a1), "=r"(a2), "=r"(a3) : "r"(XL + off));
                #pragma unroll
                for (int nt = 0; nt < 4; nt++) {
                    asm volatile(
                        "mma.sync.aligned.m16n8k16.row.col.f32.bf16.bf16.f32 "
                        "{%0,%1,%2,%3}, {%4,%5,%6,%7}, {%8,%9}, {%0,%1,%2,%3};"
                        : "+f"(acc[mt][nt][0]), "+f"(acc[mt][nt][1]),
                          "+f"(acc[mt][nt][2]), "+f"(acc[mt][nt][3])
                        : "r"(a0), "r"(a1), "r"(a2), "r"(a3),
                          "r"(bh[nt][0]), "r"(bh[nt][1]));
                }
            }
        }
        __syncthreads();
    }
#undef LOAD_STAGE
#undef STAGE_ADDR

    // epilogue: dist2 partial per (m row, warp_n), then combine
    float inv_s = s_invs;
    int rgrp = lane >> 2, qc = lane & 3;
    #pragma unroll
    for (int mt = 0; mt < 4; mt++) {
        #pragma unroll
        for (int half = 0; half < 2; half++) {
            float sum = 0.f;
            #pragma unroll
            for (int nt = 0; nt < 4; nt++) {
                int f0 = warp_n * 32 + nt * 8 + qc * 2;
                float v0 = acc[mt][nt][half * 2 + 0];
                float v1 = acc[mt][nt][half * 2 + 1];
                float d0 = s_cent[f0]     - fmaf(v0, inv_s, s_bias[f0]);
                float d1 = s_cent[f0 + 1] - fmaf(v1, inv_s, s_bias[f0 + 1]);
                sum = fmaf(d0, d0, sum);
                sum = fmaf(d1, d1, sum);
            }
            sum += __shfl_xor_sync(0xffffffffu, sum, 1);
            sum += __shfl_xor_sync(0xffffffffu, sum, 2);
            if (qc == 0)
                part[warp_m * 64 + mt * 16 + half * 8 + rgrp][warp_n] = sum;
        }
    }
    __syncthreads();
    if (tid < 128) {
        float dist2 = part[tid][0] + part[tid][1] + part[tid][2] + part[tid][3];
        out[(size_t)(bt * 128 + tid) * C_ + c] = expf(-0.5f * dist2);
    }
}

// =====================================================================
// Host
// =====================================================================
extern "C" void kernel_launch(void* const* d_in, const int* in_sizes, int n_in,
                              void* d_out, int out_size)
{
    const float* x = (const float*)d_in[0];   // [512,2048]
    const float* W = (const float*)d_in[1];   // [100,128,2048]
    const float* b = (const float*)d_in[2];   // [100,128]
    const float* u = (const float*)d_in[3];   // [100,128]
    const float* c = (const float*)d_in[4];   // [100,128]
    float* out = (float*)d_out;               // [512,100]

    cudaFuncSetAttribute(mm_kernel, cudaFuncAttributeMaxDynamicSharedMemorySize, DSMEM_SIZE);

    split_x_kernel<<<(B_ * E_) / 512, 256>>>(x);
    wsplit_v_kernel<<<dim3(C_, 2), 256>>>(W, u);
    wv_kernel<<<dim3(C_, 8), 256>>>(W);
    mm_kernel<<<dim3(4, C_), 256, DSMEM_SIZE>>>(b, c, out);
}